// round 9
// baseline (speedup 1.0000x reference)
#include <cuda_runtime.h>

// ---------------- problem constants ----------------
#define BB  8
#define SEQ 32768
#define HH  96
#define GG  384        // 4*HH
#define KW  16         // progress granularity (timesteps)
#define HC  256        // head chunk
#define NT  384        // threads per CTA

typedef unsigned long long ull;

// ---------------- scratch (device globals; allocation banned) ----------------
__device__ float g_h0seq[(size_t)BB * SEQ * HH];
__device__ float g_xp1 [(size_t)BB * SEQ * GG];
__device__ float g_h1seq[(size_t)BB * SEQ * HH];

__device__ int g_prog0[BB];
__device__ int g_progx[2 * BB];
__device__ int g_prog1[BB];

// ---------------- packed f32x2 helpers ----------------
__device__ __forceinline__ ull ffma2(ull a, ull b, ull c) {
    ull d;
    asm("fma.rn.f32x2 %0, %1, %2, %3;" : "=l"(d) : "l"(a), "l"(b), "l"(c));
    return d;
}
__device__ __forceinline__ ull pack2(float x, float y) {
    ull v;
    asm("mov.b64 %0, {%1, %2};" : "=l"(v) : "f"(x), "f"(y));
    return v;
}
__device__ __forceinline__ void unpack2(ull v, float& x, float& y) {
    asm("mov.b64 {%0, %1}, %2;" : "=f"(x), "=f"(y) : "l"(v));
}

// ---------------- raw MUFU ops (branch-free activation building blocks) ----
__device__ __forceinline__ float ex2f(float x) {
    float y;
    asm("ex2.approx.f32 %0, %1;" : "=f"(y) : "f"(x));
    return y;
}
__device__ __forceinline__ float rcpf(float x) {
    float y;
    asm("rcp.approx.f32 %0, %1;" : "=f"(y) : "f"(x));
    return y;
}
#define LOG2E 1.4426950408889634f

// tanh for epilogue: 1 - 2/(1+e^{2x})
__device__ __forceinline__ float tanh_f(float x) {
    float e = ex2f(x * (2.0f * LOG2E));
    return fmaf(-2.0f, rcpf(1.0f + e), 1.0f);
}

// ---------------- weight row -> registers ----------------
__device__ __forceinline__ void load_row(ull* w, const float* rowp) {
    const ulonglong2* wp = (const ulonglong2*)rowp;
#pragma unroll
    for (int k = 0; k < 24; k++) {
        ulonglong2 v = __ldg(wp + k);
        w[2 * k]     = v.x;
        w[2 * k + 1] = v.y;
    }
}

// dot(w_row, h[0..95]) + init ; h 16B aligned
__device__ __forceinline__ float dotv(const ull* __restrict__ w,
                                      const float* __restrict__ hsh,
                                      float init) {
    ull a0 = pack2(init, 0.0f);
    ull a1 = 0ull;
    const ulonglong2* h4 = (const ulonglong2*)hsh;
#pragma unroll
    for (int k = 0; k < 24; k++) {
        ulonglong2 hv = h4[k];
        a0 = ffma2(w[2 * k],     hv.x, a0);
        a1 = ffma2(w[2 * k + 1], hv.y, a1);
    }
    float x0, y0, x1, y1;
    unpack2(a0, x0, y0);
    unpack2(a1, x1, y1);
    return (x0 + x1) + (y0 + y1);
}

// ---------------- release/acquire flags ----------------
__device__ __forceinline__ void flag_store(int* p, int v) {
    asm volatile("st.release.gpu.global.b32 [%0], %1;" :: "l"(p), "r"(v) : "memory");
}
__device__ __forceinline__ int flag_load(const int* p) {
    int v;
    asm volatile("ld.acquire.gpu.global.b32 %0, [%1];" : "=r"(v) : "l"(p) : "memory");
    return v;
}
__device__ __forceinline__ void wait_ge(const int* p, int target) {
    while (flag_load(p) < target) { __nanosleep(32); }
}

__global__ void reset_kernel() {
    int i = threadIdx.x;
    if (i < BB)     g_prog0[i] = 0;
    if (i < 2 * BB) g_progx[i] = 0;
    if (i < BB)     g_prog1[i] = 0;
}

// =====================================================================
// Mega-kernel: 40 blocks x 384 threads, all wave-1 co-resident.
//   0..7   : layer-0 recurrence (1 batch each)
//   8..23  : xp1 workers (2 per batch, parity interleave)
//   24..31 : layer-1 recurrence (1 batch each)
//   32..39 : head workers (1 per batch)
//
// Recurrence: thread g owns gate-row g (quad=g/96). Activation is
// branch-free: act = aS * rcp(1 + ex2(dot*s2)) + dS, with
//   sigmoid rows: s2=-log2e, aS=1, dS=0
//   tanh rows   : s2=-2log2e, aS=2, dS=-1
// Epilogue threads = g<96 (i-gate rows): iv stays in-register.
// =====================================================================
__global__ void __launch_bounds__(NT, 1)
mega_kernel(const float* __restrict__ x,
            const float* __restrict__ Wih0, const float* __restrict__ Whh0,
            const float* __restrict__ bv0,
            const float* __restrict__ Wih1, const float* __restrict__ Whh1,
            const float* __restrict__ bv1,
            const float* __restrict__ h0in, const float* __restrict__ c0in,
            const float* __restrict__ head_w, const float* __restrict__ head_b,
            float* __restrict__ out)
{
    __shared__ __align__(16) float sh[KW * HH];   // 6 KB; recurrences use sh[0..384)
    const int bid = blockIdx.x;
    const int g   = threadIdx.x;

    if (bid < 8) {
        // ======== layer-0 recurrence, batch b ========
        const int b    = bid;
        const int quad = g / HH;                  // warp-uniform
        float* gsh = sh + HH;                     // f/g/o activations, 288 floats

        ull w[48];
        load_row(w, Whh0 + g * HH);
        const float wih  = __ldg(&Wih0[g]);
        const float bias = __ldg(&bv0[g]);
        const float s2 = (quad == 2) ? (-2.0f * LOG2E) : (-LOG2E);
        const float aS = (quad == 2) ? 2.0f : 1.0f;
        const float dS = (quad == 2) ? -1.0f : 0.0f;

        float c = 0.0f;
        if (g < HH) { sh[g] = __ldg(&h0in[g]); c = __ldg(&c0in[g]); }
        __syncthreads();

        const float* xb = x + (size_t)b * SEQ;
        float* hb_t = g_h0seq + (size_t)b * SEQ * HH;
        float xnext = __ldg(&xb[0]);

#pragma unroll 1
        for (int t0 = 0; t0 < SEQ; t0 += KW) {
#pragma unroll 2
            for (int tt = 0; tt < KW; tt++) {
                const int t = t0 + tt;
                float xt = xnext;
                xnext = __ldg(&xb[min(t + 1, SEQ - 1)]);

                float dot = dotv(w, sh, fmaf(xt, wih, bias));
                float e   = ex2f(dot * s2);
                float act = fmaf(aS, rcpf(1.0f + e), dS);   // branch-free
                if (quad != 0) gsh[g - HH] = act;           // predicated STS
                __syncthreads();                            // gates visible

                if (quad == 0) {                            // act == iv
                    float fv = gsh[g];
                    float gv = gsh[g + HH];
                    float ov = gsh[g + 2 * HH];
                    c = fmaf(fv, c, act * gv);
                    float hval = ov * tanh_f(c);
                    sh[g]   = hval;
                    hb_t[g] = hval;
                }
                __syncthreads();                            // h visible
                hb_t += HH;
            }
            if (g == GG - 1) flag_store(&g_prog0[b], t0 + KW);
        }
    } else if (bid < 24) {
        // ======== xp1 workers: 2 per batch ========
        const int i   = bid - 8;
        const int b   = i >> 1;
        const int par = i & 1;

        ull w[48];
        load_row(w, Wih1 + g * HH);
        const float bias = __ldg(&bv1[g]);

        const float* hbase = g_h0seq + (size_t)b * SEQ * HH;
        float* xpb = g_xp1 + (size_t)b * SEQ * GG;

#pragma unroll 1
        for (int t0 = par * KW; t0 < SEQ; t0 += 2 * KW) {
            if (g == 0) wait_ge(&g_prog0[b], t0 + KW);
            __syncthreads();
            ((float4*)sh)[g] = ((const float4*)(hbase + (size_t)t0 * HH))[g];
            __syncthreads();
            float* xpt = xpb + (size_t)t0 * GG + g;
#pragma unroll 4
            for (int s = 0; s < KW; s++) {
                xpt[0] = dotv(w, sh + s * HH, bias);
                xpt += GG;
            }
            __syncthreads();
            if (g == 0) flag_store(&g_progx[par * BB + b], t0 + KW);
        }
    } else if (bid < 32) {
        // ======== layer-1 recurrence, batch b ========
        const int b    = bid - 24;
        const int quad = g / HH;
        float* gsh = sh + HH;

        ull w[48];
        load_row(w, Whh1 + g * HH);
        const float s2 = (quad == 2) ? (-2.0f * LOG2E) : (-LOG2E);
        const float aS = (quad == 2) ? 2.0f : 1.0f;
        const float dS = (quad == 2) ? -1.0f : 0.0f;

        float c = 0.0f;
        if (g < HH) { sh[g] = __ldg(&h0in[HH + g]); c = __ldg(&c0in[HH + g]); }
        __syncthreads();

        const float* xpr = g_xp1 + (size_t)b * SEQ * GG + g;
        float* hb_t = g_h1seq + (size_t)b * SEQ * HH;

#pragma unroll 1
        for (int t0 = 0; t0 < SEQ; t0 += KW) {
            const int par = (t0 >> 4) & 1;        // (t0/KW)&1, KW=16
            if (g == 0) wait_ge(&g_progx[par * BB + b], t0 + KW);
            __syncthreads();

            float xpn = xpr[0];
#pragma unroll 2
            for (int tt = 0; tt < KW; tt++) {
                float xp = xpn;
                xpn = xpr[(tt + 1 < KW) ? GG : 0];   // prefetch within chunk

                float dot = dotv(w, sh, xp);
                float e   = ex2f(dot * s2);
                float act = fmaf(aS, rcpf(1.0f + e), dS);
                if (quad != 0) gsh[g - HH] = act;
                __syncthreads();

                if (quad == 0) {
                    float fv = gsh[g];
                    float gv = gsh[g + HH];
                    float ov = gsh[g + 2 * HH];
                    c = fmaf(fv, c, act * gv);
                    float hval = ov * tanh_f(c);
                    sh[g]   = hval;
                    hb_t[g] = hval;
                }
                __syncthreads();
                hb_t += HH;
                xpr  += GG;
            }
            if (g == GG - 1) flag_store(&g_prog1[b], t0 + KW);
        }
    } else {
        // ======== head workers ========
        const int b = bid - 32;
        float4 wv[24];
        const float4* wp = (const float4*)head_w;
#pragma unroll
        for (int k = 0; k < 24; k++) wv[k] = __ldg(&wp[k]);
        const float hb0 = __ldg(&head_b[0]);
        const float* h1b = g_h1seq + (size_t)b * SEQ * HH;
        float* ob = out + (size_t)b * SEQ;

#pragma unroll 1
        for (int t0 = 0; t0 < SEQ; t0 += HC) {
            if (g == 0) wait_ge(&g_prog1[b], t0 + HC);
            __syncthreads();
            if (g < HC) {
                const float4* hp = (const float4*)(h1b + (size_t)(t0 + g) * HH);
                float acc = 0.0f;
#pragma unroll
                for (int k = 0; k < 24; k++) {
                    float4 a = hp[k];
                    acc += a.x * wv[k].x + a.y * wv[k].y + a.z * wv[k].z + a.w * wv[k].w;
                }
                ob[t0 + g] = acc + hb0;
            }
        }
    }
}

extern "C" void kernel_launch(void* const* d_in, const int* in_sizes, int n_in,
                              void* d_out, int out_size)
{
    (void)in_sizes; (void)n_in; (void)out_size;
    const float* x      = (const float*)d_in[0];
    const float* W_ih_0 = (const float*)d_in[1];
    const float* W_hh_0 = (const float*)d_in[2];
    const float* b_0    = (const float*)d_in[3];
    const float* W_ih_1 = (const float*)d_in[4];
    const float* W_hh_1 = (const float*)d_in[5];
    const float* b_1    = (const float*)d_in[6];
    const float* h0     = (const float*)d_in[7];
    const float* c0     = (const float*)d_in[8];
    const float* head_w = (const float*)d_in[9];
    const float* head_b = (const float*)d_in[10];
    float* out = (float*)d_out;

    reset_kernel<<<1, 32>>>();
    mega_kernel<<<40, NT>>>(x, W_ih_0, W_hh_0, b_0, W_ih_1, W_hh_1, b_1,
                            h0, c0, head_w, head_b, out);
}